// round 5
// baseline (speedup 1.0000x reference)
#include <cuda_runtime.h>
#include <cstdint>

// Problem constants
static constexpr int Bb = 2048, Tt = 281, Kk = 272, Nn = 272;

#define THREADS 256          // 6 consumer warps + 2 producer warps
static constexpr int CONS_T = 192;
static constexpr int BM = 96, BN = 96, BK = 16;
static constexpr int STAGES = 5;
static constexpr int XSTR = 20;          // sX row stride (floats)
static constexpr int KITERS = Kk / BK;   // 17
static constexpr int NKB = Kk / 8;       // 34 k8-chunks
static constexpr int NNB = Nn / 8;       // 34 n8-blocks
static constexpr int NBL = BN / 8;       // 12 n-blocks per CTA

// Dynamic smem: [0,128) mbarriers (full/empty per stage), then stage data
static constexpr int XSTAGE_F = BM * XSTR;       // 1920 floats
static constexpr int WSTAGE_F = NBL * 2 * 64;    // 1536 floats
static constexpr int STAGE_F  = XSTAGE_F + WSTAGE_F;  // 3456 floats = 13824 B
static constexpr int DATA_OFF = 128;             // bytes
static constexpr int SMEM_BYTES = DATA_OFF + STAGES * STAGE_F * 4;  // 69248

// Fragment-ordered, RNA-pre-rounded weights:
// g_Wf[((e*NNB + nb)*NKB + kc)*64 + lane*2 + {0,1}] = rna(W[e][kc*8+tig+{0,4}][nb*8+gid])
__device__ float g_Wf[4 * NNB * NKB * 64];

// subject dtype flag: 1 if int64, 0 if int32
__device__ int g_subj_is64;

__global__ void probe_subject_kernel(const unsigned int* subj_words) {
    if (threadIdx.x == 0 && blockIdx.x == 0) {
        int is64 = 1;
        for (int i = 1; i < 2048; i += 2)
            if (subj_words[i] != 0u) { is64 = 0; break; }
        g_subj_is64 = is64;
    }
}

__device__ __forceinline__ uint32_t f2tf32(float f) {
    uint32_t u;
    asm("cvt.rna.tf32.f32 %0, %1;" : "=r"(u) : "f"(f));
    return u;
}

// One-time W -> fragment-ordered tf32(RNA) layout
__global__ void prep_w_frag(const float* __restrict__ W) {
    int idx = blockIdx.x * blockDim.x + threadIdx.x;
    if (idx >= 4 * NNB * NKB * 32) return;
    int lane = idx & 31;
    int kc   = (idx >> 5) % NKB;
    int nb   = ((idx >> 5) / NKB) % NNB;
    int e    = (idx >> 5) / (NKB * NNB);
    int gid = lane >> 2, tig = lane & 3;
    int n  = nb * 8 + gid;
    int k0 = kc * 8 + tig;
    const float* We = W + (size_t)e * Kk * Nn;
    float2 v;
    v.x = __uint_as_float(f2tf32(We[(size_t)k0 * Nn + n]));
    v.y = __uint_as_float(f2tf32(We[(size_t)(k0 + 4) * Nn + n]));
    *reinterpret_cast<float2*>(
        &g_Wf[(((size_t)(e * NNB + nb) * NKB + kc) * 32 + lane) * 2]) = v;
}

__device__ __forceinline__ void mma_tf32(float* d, const uint32_t* a, const uint32_t* bfr) {
    asm volatile(
        "mma.sync.aligned.m16n8k8.row.col.f32.tf32.tf32.f32 "
        "{%0,%1,%2,%3}, {%4,%5,%6,%7}, {%8,%9}, {%0,%1,%2,%3};"
        : "+f"(d[0]), "+f"(d[1]), "+f"(d[2]), "+f"(d[3])
        : "r"(a[0]), "r"(a[1]), "r"(a[2]), "r"(a[3]), "r"(bfr[0]), "r"(bfr[1]));
}

__device__ __forceinline__ void cp_async16(uint32_t dst, const void* src, int sz) {
    asm volatile("cp.async.cg.shared.global [%0], [%1], 16, %2;\n"
                 :: "r"(dst), "l"(src), "r"(sz));
}
__device__ __forceinline__ uint32_t smem_u32(const void* p) {
    uint32_t a;
    asm("{ .reg .u64 t; cvta.to.shared.u64 t, %1; cvt.u32.u64 %0, t; }" : "=r"(a) : "l"(p));
    return a;
}
__device__ __forceinline__ void mbar_init(uint32_t a, uint32_t cnt) {
    asm volatile("mbarrier.init.shared.b64 [%0], %1;" :: "r"(a), "r"(cnt) : "memory");
}
__device__ __forceinline__ void mbar_arrive(uint32_t a) {
    asm volatile("mbarrier.arrive.shared.b64 _, [%0];" :: "r"(a) : "memory");
}
__device__ __forceinline__ void mbar_arrive_cpasync(uint32_t a) {
    asm volatile("cp.async.mbarrier.arrive.noinc.shared.b64 [%0];" :: "r"(a) : "memory");
}
__device__ __forceinline__ void mbar_wait(uint32_t a, uint32_t parity) {
    uint32_t done;
    asm volatile(
        "{\n\t.reg .pred p;\n\t"
        "mbarrier.try_wait.parity.acquire.cta.shared::cta.b64 p, [%1], %2;\n\t"
        "selp.b32 %0, 1, 0, p;\n\t}"
        : "=r"(done) : "r"(a), "r"(parity) : "memory");
    if (!done) {
        asm volatile(
            "{\n\t.reg .pred P1;\n\t"
            "W_%=:\n\t"
            "mbarrier.try_wait.parity.acquire.cta.shared::cta.b64 P1, [%0], %1, 0x989680;\n\t"
            "@P1 bra.uni D_%=;\n\t"
            "bra.uni W_%=;\n\t"
            "D_%=:\n\t}"
            :: "r"(a), "r"(parity) : "memory");
    }
}

__global__ __launch_bounds__(THREADS, 2) void subj_gemm_kernel(
    const float* __restrict__ X, const void* __restrict__ subj,
    const float* __restrict__ bias, float* __restrict__ out)
{
    extern __shared__ float smem_f[];
    float* data = smem_f + DATA_OFF / 4;

    const int b   = blockIdx.z;
    const int m0  = blockIdx.y * BM;
    const int nb0 = blockIdx.x * NBL;
    const int n0  = nb0 * 8;

    int s;
    if (g_subj_is64) s = (int)((const long long*)subj)[b];
    else             s = ((const int*)subj)[b];

    const float* Xb  = X + (size_t)b * Tt * Kk;
    const float* Wfe = g_Wf + (size_t)s * NNB * NKB * 64;

    const int tid  = threadIdx.x;
    const int lane = tid & 31;

    const uint32_t mbase = smem_u32(smem_f);
    // full[st] = mbase + st*16, empty[st] = mbase + st*16 + 8
    if (tid == 0) {
#pragma unroll
        for (int st = 0; st < STAGES; ++st) {
            mbar_init(mbase + st * 16, 128);     // full: 64 STS-arrives + 64 cp.async arrives
            mbar_init(mbase + st * 16 + 8, 6);   // empty: 1 per consumer warp
        }
    }
    __syncthreads();

    if (tid < CONS_T) {
        // ================= CONSUMER =================
        const int warp = tid >> 5;     // 0..5
        const int wm   = warp / 3;     // 0..1
        const int wn   = warp % 3;     // 0..2
        const int gid  = lane >> 2;
        const int tig  = lane & 3;

        float acc[3][4][4];
#pragma unroll
        for (int i = 0; i < 3; ++i)
#pragma unroll
            for (int j = 0; j < 4; ++j)
#pragma unroll
                for (int k = 0; k < 4; ++k) acc[i][j][k] = 0.f;

        int ph[STAGES];
#pragma unroll
        for (int i = 0; i < STAGES; ++i) ph[i] = 0;

        for (int kk = 0; kk < KITERS; ++kk) {
            const int st = kk % STAGES;
            mbar_wait(mbase + st * 16, ph[st]);
            ph[st] ^= 1;

            const float* xbase = data + st * STAGE_F;
            const float* wbase = xbase + XSTAGE_F;
#pragma unroll
            for (int ks = 0; ks < 2; ++ks) {
                const int kb = ks * 8;
                uint32_t af[3][4];
#pragma unroll
                for (int mi = 0; mi < 3; ++mi) {
                    int r = wm * 48 + mi * 16 + gid;
                    af[mi][0] = __float_as_uint(xbase[(r    ) * XSTR + kb + tig    ]);
                    af[mi][1] = __float_as_uint(xbase[(r + 8) * XSTR + kb + tig    ]);
                    af[mi][2] = __float_as_uint(xbase[(r    ) * XSTR + kb + tig + 4]);
                    af[mi][3] = __float_as_uint(xbase[(r + 8) * XSTR + kb + tig + 4]);
                }
                uint32_t bf[4][2];
#pragma unroll
                for (int ni = 0; ni < 4; ++ni) {
                    int nbl = wn * 4 + ni;
                    float2 v = *reinterpret_cast<const float2*>(
                        wbase + (nbl * 2 + ks) * 64 + lane * 2);
                    bf[ni][0] = __float_as_uint(v.x);
                    bf[ni][1] = __float_as_uint(v.y);
                }
#pragma unroll
                for (int mi = 0; mi < 3; ++mi)
#pragma unroll
                    for (int ni = 0; ni < 4; ++ni)
                        mma_tf32(acc[mi][ni], af[mi], bf[ni]);
            }
            __syncwarp();
            if (lane == 0) mbar_arrive(mbase + st * 16 + 8);   // empty
        }

        // ---- epilogue: bias add + guarded float2 stores ----
        float* outb = out + (size_t)b * Tt * Nn;
#pragma unroll
        for (int mi = 0; mi < 3; ++mi) {
            int r0 = m0 + wm * 48 + mi * 16 + gid;
#pragma unroll
            for (int ni = 0; ni < 4; ++ni) {
                int n = n0 + wn * 32 + ni * 8 + tig * 2;
                if (n < Nn) {
                    float bv0 = bias[s * Nn + n];
                    float bv1 = bias[s * Nn + n + 1];
                    if (r0 < Tt) {
                        float2 v = make_float2(acc[mi][ni][0] + bv0, acc[mi][ni][1] + bv1);
                        *reinterpret_cast<float2*>(outb + (size_t)r0 * Nn + n) = v;
                    }
                    if (r0 + 8 < Tt) {
                        float2 v = make_float2(acc[mi][ni][2] + bv0, acc[mi][ni][3] + bv1);
                        *reinterpret_cast<float2*>(outb + (size_t)(r0 + 8) * Nn + n) = v;
                    }
                }
            }
        }
    } else {
        // ================= PRODUCER (warps 6,7; 64 threads) =================
        const int ptid = tid - CONS_T;   // 0..63

        // fixed X task coordinates: 6 tasks (96 rows x 4 chunks / 64 threads)
        int xrow[6], xj[6], xm[6];
#pragma unroll
        for (int it = 0; it < 6; ++it) {
            int idx = ptid + 64 * it;
            xrow[it] = idx >> 2;
            xj[it]   = idx & 3;
            int m = m0 + xrow[it];
            xm[it] = (m < Tt) ? m : (Tt - 1);
        }
        // fixed W task coordinates: 6 tasks (12 nbl x 2 ks x 16 ch / 64 threads)
        int wnbl[6], wks[6], wch[6];
#pragma unroll
        for (int it = 0; it < 6; ++it) {
            int idx = ptid + 64 * it;
            wnbl[it] = idx >> 5;
            wks[it]  = (idx >> 4) & 1;
            wch[it]  = idx & 15;
        }

        int ph[STAGES];
#pragma unroll
        for (int i = 0; i < STAGES; ++i) ph[i] = 0;

        for (int i = 0; i < KITERS; ++i) {
            const int st = i % STAGES;
            if (i >= STAGES) {
                mbar_wait(mbase + st * 16 + 8, ph[st]);   // empty
                ph[st] ^= 1;
            }
            const int k0  = i * BK;
            const int kc0 = i * 2;
            float* xbase = data + st * STAGE_F;
            float* wbase = xbase + XSTAGE_F;

            // X: LDG.128 batch
            float4 xv[6];
#pragma unroll
            for (int it = 0; it < 6; ++it)
                xv[it] = *reinterpret_cast<const float4*>(
                    Xb + (size_t)xm[it] * Kk + k0 + 4 * xj[it]);
            // cvt + STS
#pragma unroll
            for (int it = 0; it < 6; ++it) {
                uint4 u;
                u.x = f2tf32(xv[it].x); u.y = f2tf32(xv[it].y);
                u.z = f2tf32(xv[it].z); u.w = f2tf32(xv[it].w);
                *reinterpret_cast<uint4*>(xbase + xrow[it] * XSTR + 4 * xj[it]) = u;
            }
            mbar_arrive(mbase + st * 16);   // X visibility arrive (release)

            // W: cp.async batch, then async arrive
#pragma unroll
            for (int it = 0; it < 6; ++it) {
                int nb = nb0 + wnbl[it];
                bool v = (nb < NNB);
                const float* src = Wfe + ((size_t)(v ? nb : 0) * NKB + kc0 + wks[it]) * 64
                                   + wch[it] * 4;
                uint32_t dst = smem_u32(wbase + (wnbl[it] * 2 + wks[it]) * 64 + wch[it] * 4);
                cp_async16(dst, src, v ? 16 : 0);
            }
            mbar_arrive_cpasync(mbase + st * 16);
        }
    }
}

extern "C" void kernel_launch(void* const* d_in, const int* in_sizes, int n_in,
                              void* d_out, int out_size) {
    const float* X    = (const float*)d_in[0];
    const void*  subj = d_in[1];
    const float* W    = (const float*)d_in[2];
    const float* bias = (const float*)d_in[3];
    float* out = (float*)d_out;

    cudaFuncSetAttribute(subj_gemm_kernel,
                         cudaFuncAttributeMaxDynamicSharedMemorySize, SMEM_BYTES);

    probe_subject_kernel<<<1, 32>>>((const unsigned int*)subj);

    int prep_threads = 4 * NNB * NKB * 32;
    prep_w_frag<<<(prep_threads + 255) / 256, 256>>>(W);

    dim3 grid((Nn + BN - 1) / BN,   // 3
              (Tt + BM - 1) / BM,   // 3
              Bb);                  // 2048
    subj_gemm_kernel<<<grid, dim3(THREADS), SMEM_BYTES>>>(X, subj, bias, out);
}

// round 6
// speedup vs baseline: 1.7624x; 1.7624x over previous
#include <cuda_runtime.h>
#include <cuda_fp16.h>
#include <cstdint>

// Problem constants
static constexpr int Bb = 2048, Tt = 281, Kk = 272, Nn = 272;

#define THREADS 192
static constexpr int BM = 96, BN = 96, BK = 32;      // BK floats of K per stage
static constexpr int STAGES = 4;
static constexpr int KIT = (Kk + BK - 1) / BK;       // 9 iterations (last is half)
static constexpr int NKC = Kk / 16;                  // 17 k16-chunks
static constexpr int NNB = Nn / 8;                   // 34 n8-blocks
static constexpr int NBL = BN / 8;                   // 12 n-blocks per CTA

// SMEM layout (bytes, dynamic):
//   per stage: X tile 96 rows x 80B (32 halfs data + pad)  = 7680
//              W tile 12 nbl x 2 ks x 256B (frag-ordered)  = 6144
static constexpr int XROW_B   = 80;
static constexpr int XSTAGE_B = BM * XROW_B;          // 7680
static constexpr int WSTAGE_B = NBL * 2 * 256;        // 6144
static constexpr int STAGE_B  = XSTAGE_B + WSTAGE_B;  // 13824
static constexpr int SMEM_BYTES = STAGES * STAGE_B;   // 55296

// Fragment-ordered fp16(RN) weights: per (e, nb, kc16, lane) one uint2
//   .x = {W[k0+2tig][n], W[k0+2tig+1][n]}  (low half = lower k)
//   .y = {W[k0+2tig+8][n], W[k0+2tig+9][n]}
// where k0 = kc*16, n = nb*8 + gid
__device__ uint2 g_Wf[4 * NNB * NKC * 32];

// subject dtype flag: 1 if int64, 0 if int32 (jax may demote int64 -> int32)
__device__ int g_subj_is64;

__global__ void probe_subject_kernel(const unsigned int* subj_words) {
    if (threadIdx.x == 0 && blockIdx.x == 0) {
        int is64 = 1;
        for (int i = 1; i < 2048; i += 2)
            if (subj_words[i] != 0u) { is64 = 0; break; }
        g_subj_is64 = is64;
    }
}

// One-time W -> fragment-ordered fp16 layout
__global__ void prep_w_frag(const float* __restrict__ W) {
    int idx = blockIdx.x * blockDim.x + threadIdx.x;
    if (idx >= 4 * NNB * NKC * 32) return;
    int lane = idx & 31;
    int kc   = (idx >> 5) % NKC;
    int nb   = ((idx >> 5) / NKC) % NNB;
    int e    = (idx >> 5) / (NKC * NNB);
    int gid = lane >> 2, tig = lane & 3;
    int n  = nb * 8 + gid;
    int k0 = kc * 16 + 2 * tig;
    const float* We = W + (size_t)e * Kk * Nn;
    __half2 h0 = __floats2half2_rn(We[(size_t)(k0    ) * Nn + n],
                                   We[(size_t)(k0 + 1) * Nn + n]);
    __half2 h1 = __floats2half2_rn(We[(size_t)(k0 + 8) * Nn + n],
                                   We[(size_t)(k0 + 9) * Nn + n]);
    uint2 u;
    u.x = *reinterpret_cast<uint32_t*>(&h0);
    u.y = *reinterpret_cast<uint32_t*>(&h1);
    g_Wf[((size_t)(e * NNB + nb) * NKC + kc) * 32 + lane] = u;
}

__device__ __forceinline__ void mma_f16(float* d, const uint32_t* a, const uint32_t* bfr) {
    asm volatile(
        "mma.sync.aligned.m16n8k16.row.col.f32.f16.f16.f32 "
        "{%0,%1,%2,%3}, {%4,%5,%6,%7}, {%8,%9}, {%0,%1,%2,%3};"
        : "+f"(d[0]), "+f"(d[1]), "+f"(d[2]), "+f"(d[3])
        : "r"(a[0]), "r"(a[1]), "r"(a[2]), "r"(a[3]), "r"(bfr[0]), "r"(bfr[1]));
}

__device__ __forceinline__ void cp_async16(uint32_t dst, const void* src, int sz) {
    asm volatile("cp.async.cg.shared.global [%0], [%1], 16, %2;\n"
                 :: "r"(dst), "l"(src), "r"(sz));
}

__global__ __launch_bounds__(THREADS) void subj_gemm_kernel(
    const float* __restrict__ X, const void* __restrict__ subj,
    const float* __restrict__ bias, float* __restrict__ out)
{
    extern __shared__ char smem[];

    const int b   = blockIdx.z;
    const int m0  = blockIdx.y * BM;
    const int nb0 = blockIdx.x * NBL;
    const int n0  = nb0 * 8;

    int s;
    if (g_subj_is64) s = (int)((const long long*)subj)[b];
    else             s = ((const int*)subj)[b];

    const float* Xb  = X + (size_t)b * Tt * Kk;
    const char*  Wfe = reinterpret_cast<const char*>(g_Wf + (size_t)s * NNB * NKC * 32);

    const int tid  = threadIdx.x;
    const int lane = tid & 31;
    const int warp = tid >> 5;     // 0..5
    const int wm   = warp / 3;     // 0..1  (warp rows of 48)
    const int wn   = warp % 3;     // 0..2  (warp cols of 32 = 4 n-blocks)
    const int gid  = lane >> 2;    // 0..7
    const int tig  = lane & 3;     // 0..3

    // X loader coords: thread handles one row-half (16 floats)
    const int xrow = tid >> 1;           // 0..95
    const int xh   = tid & 1;            // 0..1 (which 16-float half of the 32-float window)
    const int xm   = (m0 + xrow < Tt) ? (m0 + xrow) : (Tt - 1);

    float acc[3][4][4];
#pragma unroll
    for (int i = 0; i < 3; ++i)
#pragma unroll
        for (int j = 0; j < 4; ++j)
#pragma unroll
            for (int k = 0; k < 4; ++k) acc[i][j][k] = 0.f;

    // ---- X: LDG.128 x4 for k-window ci into regs (guarded for last half-stage) ----
    auto ldg_x = [&](int ci, float4* xv) {
        const int k0 = ci * BK + xh * 16;
        if (k0 < Kk) {
            const float* src = Xb + (size_t)xm * Kk + k0;
            xv[0] = *reinterpret_cast<const float4*>(src);
            xv[1] = *reinterpret_cast<const float4*>(src + 4);
            xv[2] = *reinterpret_cast<const float4*>(src + 8);
            xv[3] = *reinterpret_cast<const float4*>(src + 12);
        }
    };
    // ---- X: cvt fp32->fp16 RN + 2x STS.128 ----
    auto sts_x = [&](int st, const float4* xv) {
        char* xbase = smem + st * STAGE_B;
        uint4 u0, u1;
        __half2 h;
        h = __floats2half2_rn(xv[0].x, xv[0].y); u0.x = *reinterpret_cast<uint32_t*>(&h);
        h = __floats2half2_rn(xv[0].z, xv[0].w); u0.y = *reinterpret_cast<uint32_t*>(&h);
        h = __floats2half2_rn(xv[1].x, xv[1].y); u0.z = *reinterpret_cast<uint32_t*>(&h);
        h = __floats2half2_rn(xv[1].z, xv[1].w); u0.w = *reinterpret_cast<uint32_t*>(&h);
        h = __floats2half2_rn(xv[2].x, xv[2].y); u1.x = *reinterpret_cast<uint32_t*>(&h);
        h = __floats2half2_rn(xv[2].z, xv[2].w); u1.y = *reinterpret_cast<uint32_t*>(&h);
        h = __floats2half2_rn(xv[3].x, xv[3].y); u1.z = *reinterpret_cast<uint32_t*>(&h);
        h = __floats2half2_rn(xv[3].z, xv[3].w); u1.w = *reinterpret_cast<uint32_t*>(&h);
        *reinterpret_cast<uint4*>(xbase + xrow * XROW_B + xh * 32     ) = u0;
        *reinterpret_cast<uint4*>(xbase + xrow * XROW_B + xh * 32 + 16) = u1;
    };
    // ---- W: cp.async fragment chunks for k-window ci (2 x k16) ----
    auto ldw = [&](int st, int ci) {
        char* wbase = smem + st * STAGE_B + XSTAGE_B;
#pragma unroll
        for (int it = 0; it < 2; ++it) {
            int c   = tid + it * THREADS;         // 0..383
            int nbl = c >> 5;                     // 0..11
            int ks  = (c >> 4) & 1;               // 0..1
            int ch  = c & 15;                     // 0..15 (16B chunks of 256B block)
            int nb  = nb0 + nbl;
            int kc  = ci * 2 + ks;
            bool v  = (nb < NNB) && (kc < NKC);
            const char* src = Wfe + ((size_t)(v ? nb : 0) * NKC + (v ? kc : 0)) * 256 + ch * 16;
            uint32_t dst = (uint32_t)__cvta_generic_to_shared(
                wbase + (nbl * 2 + ks) * 256 + ch * 16);
            cp_async16(dst, src, v ? 16 : 0);
        }
    };

    // ---- prologue: stages 0,1 fully; stage 2 W async + X held in regs ----
    float4 xv[4], xvP[4];
    ldg_x(0, xv); sts_x(0, xv);
    ldw(0, 0);
    asm volatile("cp.async.commit_group;" ::: "memory");
    ldg_x(1, xv); sts_x(1, xv);
    ldw(1, 1);
    asm volatile("cp.async.commit_group;" ::: "memory");
    ldg_x(2, xvP);               // STS happens at iter 0
    ldw(2, 2);
    asm volatile("cp.async.commit_group;" ::: "memory");

    for (int kk = 0; kk < KIT; ++kk) {
        asm volatile("cp.async.wait_group 2;" ::: "memory");
        __syncthreads();

        // STS X regs (loaded last iter / prologue) for stage kk+2
        const int s2 = kk + 2;
        if (s2 < KIT) sts_x(s2 % STAGES, xvP);
        // Issue X LDG + W cp.async for stage kk+3
        const int s3 = kk + 3;
        if (s3 < KIT) {
            ldg_x(s3, xvP);
            ldw(s3 % STAGES, s3);
        }
        asm volatile("cp.async.commit_group;" ::: "memory");

        // ---- compute stage kk: nk16 k16-steps ----
        const int st = kk % STAGES;
        const char* xbase = smem + st * STAGE_B;
        const char* wbase = xbase + XSTAGE_B;
        const int nk16 = (kk == KIT - 1) ? 1 : 2;   // last window is 16 wide
#pragma unroll
        for (int ks = 0; ks < 2; ++ks) {
            if (ks >= nk16) break;
            const int kb = ks * 32;   // byte offset of k16 step in X row

            uint32_t af[3][4];
#pragma unroll
            for (int mi = 0; mi < 3; ++mi) {
                int r = wm * 48 + mi * 16 + gid;
                const char* rp0 = xbase + (r    ) * XROW_B + kb + 4 * tig;
                const char* rp1 = xbase + (r + 8) * XROW_B + kb + 4 * tig;
                af[mi][0] = *reinterpret_cast<const uint32_t*>(rp0);
                af[mi][1] = *reinterpret_cast<const uint32_t*>(rp1);
                af[mi][2] = *reinterpret_cast<const uint32_t*>(rp0 + 16);
                af[mi][3] = *reinterpret_cast<const uint32_t*>(rp1 + 16);
            }
            uint32_t bf[4][2];
#pragma unroll
            for (int ni = 0; ni < 4; ++ni) {
                int nbl = wn * 4 + ni;
                uint2 v = *reinterpret_cast<const uint2*>(
                    wbase + (nbl * 2 + ks) * 256 + lane * 8);
                bf[ni][0] = v.x;
                bf[ni][1] = v.y;
            }
#pragma unroll
            for (int mi = 0; mi < 3; ++mi)
#pragma unroll
                for (int ni = 0; ni < 4; ++ni)
                    mma_f16(acc[mi][ni], af[mi], bf[ni]);
        }
    }

    // ---- epilogue: bias add + guarded float2 stores ----
    float* outb = out + (size_t)b * Tt * Nn;
#pragma unroll
    for (int mi = 0; mi < 3; ++mi) {
        int r0 = m0 + wm * 48 + mi * 16 + gid;
#pragma unroll
        for (int ni = 0; ni < 4; ++ni) {
            int n = n0 + wn * 32 + ni * 8 + tig * 2;
            if (n < Nn) {   // n even, Nn even -> n+1 also valid
                float bv0 = bias[s * Nn + n];
                float bv1 = bias[s * Nn + n + 1];
                if (r0 < Tt) {
                    float2 v = make_float2(acc[mi][ni][0] + bv0, acc[mi][ni][1] + bv1);
                    *reinterpret_cast<float2*>(outb + (size_t)r0 * Nn + n) = v;
                }
                if (r0 + 8 < Tt) {
                    float2 v = make_float2(acc[mi][ni][2] + bv0, acc[mi][ni][3] + bv1);
                    *reinterpret_cast<float2*>(outb + (size_t)(r0 + 8) * Nn + n) = v;
                }
            }
        }
    }
}

extern "C" void kernel_launch(void* const* d_in, const int* in_sizes, int n_in,
                              void* d_out, int out_size) {
    const float* X    = (const float*)d_in[0];
    const void*  subj = d_in[1];
    const float* W    = (const float*)d_in[2];
    const float* bias = (const float*)d_in[3];
    float* out = (float*)d_out;

    cudaFuncSetAttribute(subj_gemm_kernel,
                         cudaFuncAttributeMaxDynamicSharedMemorySize, SMEM_BYTES);

    probe_subject_kernel<<<1, 32>>>((const unsigned int*)subj);

    int prep_threads = 4 * NNB * NKC * 32;   // 73984
    prep_w_frag<<<(prep_threads + 255) / 256, 256>>>(W);

    dim3 grid((Nn + BN - 1) / BN,   // 3
              (Tt + BM - 1) / BM,   // 3
              Bb);                  // 2048
    subj_gemm_kernel<<<grid, dim3(THREADS), SMEM_BYTES>>>(X, subj, bias, out);
}

// round 7
// speedup vs baseline: 1.9271x; 1.0935x over previous
#include <cuda_runtime.h>
#include <cuda_fp16.h>
#include <cstdint>

// Problem constants
static constexpr int Bb = 2048, Tt = 281, Kk = 272, Nn = 272;

#define THREADS 192
static constexpr int BM = 96, BN = 96, BK = 32;      // BK floats of K per stage
static constexpr int STAGES = 4;
static constexpr int KIT = (Kk + BK - 1) / BK;       // 9 iterations (last is half)
static constexpr int NKC = Kk / 16;                  // 17 k16-chunks
static constexpr int NNB = Nn / 8;                   // 34 n8-blocks
static constexpr int NBL = BN / 8;                   // 12 n-blocks per CTA

// SMEM layout (bytes, dynamic):
static constexpr int XROW_B   = 80;
static constexpr int XSTAGE_B = BM * XROW_B;          // 7680
static constexpr int WSTAGE_B = NBL * 2 * 256;        // 6144
static constexpr int STAGE_B  = XSTAGE_B + WSTAGE_B;  // 13824
static constexpr int SMEM_BYTES = STAGES * STAGE_B;   // 55296

// Fragment-ordered fp16(RN) weights: per (e, nb, kc16, lane) one uint2
__device__ uint2 g_Wf[4 * NNB * NKC * 32];

// subject dtype flag: 1 if int64, 0 if int32 (jax may demote int64 -> int32)
__device__ int g_subj_is64;

// One-time W -> fragment-ordered fp16 layout. Block 0 thread 0 also probes
// the subject dtype (independent work, merged to keep launches-per-call at 2
// so ncu -s 5 -c 1 lands on the main kernel).
__global__ void prep_w_frag(const float* __restrict__ W,
                            const unsigned int* __restrict__ subj_words) {
    if (blockIdx.x == 0 && threadIdx.x == 0) {
        int is64 = 1;
        for (int i = 1; i < 2048; i += 2)
            if (subj_words[i] != 0u) { is64 = 0; break; }
        g_subj_is64 = is64;
    }
    int idx = blockIdx.x * blockDim.x + threadIdx.x;
    if (idx >= 4 * NNB * NKC * 32) return;
    int lane = idx & 31;
    int kc   = (idx >> 5) % NKC;
    int nb   = ((idx >> 5) / NKC) % NNB;
    int e    = (idx >> 5) / (NKC * NNB);
    int gid = lane >> 2, tig = lane & 3;
    int n  = nb * 8 + gid;
    int k0 = kc * 16 + 2 * tig;
    const float* We = W + (size_t)e * Kk * Nn;
    __half2 h0 = __floats2half2_rn(We[(size_t)(k0    ) * Nn + n],
                                   We[(size_t)(k0 + 1) * Nn + n]);
    __half2 h1 = __floats2half2_rn(We[(size_t)(k0 + 8) * Nn + n],
                                   We[(size_t)(k0 + 9) * Nn + n]);
    uint2 u;
    u.x = *reinterpret_cast<uint32_t*>(&h0);
    u.y = *reinterpret_cast<uint32_t*>(&h1);
    g_Wf[((size_t)(e * NNB + nb) * NKC + kc) * 32 + lane] = u;
}

__device__ __forceinline__ void mma_f16(float* d, const uint32_t* a, const uint32_t* bfr) {
    asm volatile(
        "mma.sync.aligned.m16n8k16.row.col.f32.f16.f16.f32 "
        "{%0,%1,%2,%3}, {%4,%5,%6,%7}, {%8,%9}, {%0,%1,%2,%3};"
        : "+f"(d[0]), "+f"(d[1]), "+f"(d[2]), "+f"(d[3])
        : "r"(a[0]), "r"(a[1]), "r"(a[2]), "r"(a[3]), "r"(bfr[0]), "r"(bfr[1]));
}

__device__ __forceinline__ void cp_async16(uint32_t dst, const void* src, int sz) {
    asm volatile("cp.async.cg.shared.global [%0], [%1], 16, %2;\n"
                 :: "r"(dst), "l"(src), "r"(sz));
}

__global__ __launch_bounds__(THREADS, 3) void subj_gemm_kernel(
    const float* __restrict__ X, const void* __restrict__ subj,
    const float* __restrict__ bias, float* __restrict__ out)
{
    extern __shared__ char smem[];

    const int b   = blockIdx.z;
    const int m0  = blockIdx.y * BM;
    const int nb0 = blockIdx.x * NBL;
    const int n0  = nb0 * 8;

    int s;
    if (g_subj_is64) s = (int)((const long long*)subj)[b];
    else             s = ((const int*)subj)[b];

    const float* Xb  = X + (size_t)b * Tt * Kk;
    const char*  Wfe = reinterpret_cast<const char*>(g_Wf + (size_t)s * NNB * NKC * 32);

    const int tid  = threadIdx.x;
    const int lane = tid & 31;
    const int warp = tid >> 5;     // 0..5
    const int wm   = warp / 3;     // 0..1  (warp rows of 48)
    const int wn   = warp % 3;     // 0..2  (warp cols of 32 = 4 n-blocks)
    const int gid  = lane >> 2;    // 0..7
    const int tig  = lane & 3;     // 0..3

    // X loader coords: thread handles one row-half (16 floats)
    const int xrow = tid >> 1;           // 0..95
    const int xh   = tid & 1;            // which 16-float half of the 32-float window
    const int xm   = (m0 + xrow < Tt) ? (m0 + xrow) : (Tt - 1);

    float acc[3][4][4];
#pragma unroll
    for (int i = 0; i < 3; ++i)
#pragma unroll
        for (int j = 0; j < 4; ++j)
#pragma unroll
            for (int k = 0; k < 4; ++k) acc[i][j][k] = 0.f;

    auto ldg_x = [&](int ci, float4* xv) {
        const int k0 = ci * BK + xh * 16;
        if (k0 < Kk) {
            const float* src = Xb + (size_t)xm * Kk + k0;
            xv[0] = *reinterpret_cast<const float4*>(src);
            xv[1] = *reinterpret_cast<const float4*>(src + 4);
            xv[2] = *reinterpret_cast<const float4*>(src + 8);
            xv[3] = *reinterpret_cast<const float4*>(src + 12);
        }
    };
    auto sts_x = [&](int st, const float4* xv) {
        char* xbase = smem + st * STAGE_B;
        uint4 u0, u1;
        __half2 h;
        h = __floats2half2_rn(xv[0].x, xv[0].y); u0.x = *reinterpret_cast<uint32_t*>(&h);
        h = __floats2half2_rn(xv[0].z, xv[0].w); u0.y = *reinterpret_cast<uint32_t*>(&h);
        h = __floats2half2_rn(xv[1].x, xv[1].y); u0.z = *reinterpret_cast<uint32_t*>(&h);
        h = __floats2half2_rn(xv[1].z, xv[1].w); u0.w = *reinterpret_cast<uint32_t*>(&h);
        h = __floats2half2_rn(xv[2].x, xv[2].y); u1.x = *reinterpret_cast<uint32_t*>(&h);
        h = __floats2half2_rn(xv[2].z, xv[2].w); u1.y = *reinterpret_cast<uint32_t*>(&h);
        h = __floats2half2_rn(xv[3].x, xv[3].y); u1.z = *reinterpret_cast<uint32_t*>(&h);
        h = __floats2half2_rn(xv[3].z, xv[3].w); u1.w = *reinterpret_cast<uint32_t*>(&h);
        *reinterpret_cast<uint4*>(xbase + xrow * XROW_B + xh * 32     ) = u0;
        *reinterpret_cast<uint4*>(xbase + xrow * XROW_B + xh * 32 + 16) = u1;
    };
    auto ldw = [&](int st, int ci) {
        char* wbase = smem + st * STAGE_B + XSTAGE_B;
#pragma unroll
        for (int it = 0; it < 2; ++it) {
            int c   = tid + it * THREADS;         // 0..383
            int nbl = c >> 5;
            int ks  = (c >> 4) & 1;
            int ch  = c & 15;
            int nb  = nb0 + nbl;
            int kc  = ci * 2 + ks;
            bool v  = (nb < NNB) && (kc < NKC);
            const char* src = Wfe + ((size_t)(v ? nb : 0) * NKC + (v ? kc : 0)) * 256 + ch * 16;
            uint32_t dst = (uint32_t)__cvta_generic_to_shared(
                wbase + (nbl * 2 + ks) * 256 + ch * 16);
            cp_async16(dst, src, v ? 16 : 0);
        }
    };

    // ---- prologue ----
    float4 xv[4], xvP[4];
    ldg_x(0, xv); sts_x(0, xv);
    ldw(0, 0);
    asm volatile("cp.async.commit_group;" ::: "memory");
    ldg_x(1, xv); sts_x(1, xv);
    ldw(1, 1);
    asm volatile("cp.async.commit_group;" ::: "memory");
    ldg_x(2, xvP);               // STS happens at iter 0
    ldw(2, 2);
    asm volatile("cp.async.commit_group;" ::: "memory");

    for (int kk = 0; kk < KIT; ++kk) {
        asm volatile("cp.async.wait_group 2;" ::: "memory");
        __syncthreads();

        const int st = kk % STAGES;
        const char* xbase = smem + st * STAGE_B;
        const char* wbase = xbase + XSTAGE_B;

        // ---- load ALL W fragments (both k16 steps) up front ----
        uint32_t bf[2][4][2];
#pragma unroll
        for (int ks = 0; ks < 2; ++ks)
#pragma unroll
            for (int ni = 0; ni < 4; ++ni) {
                int nbl = wn * 4 + ni;
                uint2 v = *reinterpret_cast<const uint2*>(
                    wbase + (nbl * 2 + ks) * 256 + lane * 8);
                bf[ks][ni][0] = v.x;
                bf[ks][ni][1] = v.y;
            }

        // ---- X fragments ks0 + MMA burst 0 ----
        uint32_t af[3][4];
#pragma unroll
        for (int mi = 0; mi < 3; ++mi) {
            int r = wm * 48 + mi * 16 + gid;
            const char* rp0 = xbase + (r    ) * XROW_B + 4 * tig;
            const char* rp1 = xbase + (r + 8) * XROW_B + 4 * tig;
            af[mi][0] = *reinterpret_cast<const uint32_t*>(rp0);
            af[mi][1] = *reinterpret_cast<const uint32_t*>(rp1);
            af[mi][2] = *reinterpret_cast<const uint32_t*>(rp0 + 16);
            af[mi][3] = *reinterpret_cast<const uint32_t*>(rp1 + 16);
        }
#pragma unroll
        for (int mi = 0; mi < 3; ++mi)
#pragma unroll
            for (int ni = 0; ni < 4; ++ni)
                mma_f16(acc[mi][ni], af[mi], bf[0][ni]);

        // ---- memory issue phase (overlaps MMA tail) ----
        const int s2 = kk + 2;
        if (s2 < KIT) sts_x(s2 % STAGES, xvP);
        const int s3 = kk + 3;
        if (s3 < KIT) {
            ldg_x(s3, xvP);
            ldw(s3 % STAGES, s3);
        }
        asm volatile("cp.async.commit_group;" ::: "memory");

        // ---- X fragments ks1 + MMA burst 1 (skip on last half-window) ----
        if (kk != KIT - 1) {
#pragma unroll
            for (int mi = 0; mi < 3; ++mi) {
                int r = wm * 48 + mi * 16 + gid;
                const char* rp0 = xbase + (r    ) * XROW_B + 32 + 4 * tig;
                const char* rp1 = xbase + (r + 8) * XROW_B + 32 + 4 * tig;
                af[mi][0] = *reinterpret_cast<const uint32_t*>(rp0);
                af[mi][1] = *reinterpret_cast<const uint32_t*>(rp1);
                af[mi][2] = *reinterpret_cast<const uint32_t*>(rp0 + 16);
                af[mi][3] = *reinterpret_cast<const uint32_t*>(rp1 + 16);
            }
#pragma unroll
            for (int mi = 0; mi < 3; ++mi)
#pragma unroll
                for (int ni = 0; ni < 4; ++ni)
                    mma_f16(acc[mi][ni], af[mi], bf[1][ni]);
        }
    }

    // ---- epilogue: bias add + guarded float2 stores ----
    float* outb = out + (size_t)b * Tt * Nn;
#pragma unroll
    for (int mi = 0; mi < 3; ++mi) {
        int r0 = m0 + wm * 48 + mi * 16 + gid;
#pragma unroll
        for (int ni = 0; ni < 4; ++ni) {
            int n = n0 + wn * 32 + ni * 8 + tig * 2;
            if (n < Nn) {
                float bv0 = bias[s * Nn + n];
                float bv1 = bias[s * Nn + n + 1];
                if (r0 < Tt) {
                    float2 v = make_float2(acc[mi][ni][0] + bv0, acc[mi][ni][1] + bv1);
                    *reinterpret_cast<float2*>(outb + (size_t)r0 * Nn + n) = v;
                }
                if (r0 + 8 < Tt) {
                    float2 v = make_float2(acc[mi][ni][2] + bv0, acc[mi][ni][3] + bv1);
                    *reinterpret_cast<float2*>(outb + (size_t)(r0 + 8) * Nn + n) = v;
                }
            }
        }
    }
}

extern "C" void kernel_launch(void* const* d_in, const int* in_sizes, int n_in,
                              void* d_out, int out_size) {
    const float* X    = (const float*)d_in[0];
    const void*  subj = d_in[1];
    const float* W    = (const float*)d_in[2];
    const float* bias = (const float*)d_in[3];
    float* out = (float*)d_out;

    cudaFuncSetAttribute(subj_gemm_kernel,
                         cudaFuncAttributeMaxDynamicSharedMemorySize, SMEM_BYTES);

    int prep_threads = 4 * NNB * NKC * 32;   // 73984
    prep_w_frag<<<(prep_threads + 255) / 256, 256>>>(W, (const unsigned int*)subj);

    dim3 grid((Nn + BN - 1) / BN,   // 3
              (Tt + BM - 1) / BM,   // 3
              Bb);                  // 2048
    subj_gemm_kernel<<<grid, dim3(THREADS), SMEM_BYTES>>>(X, subj, bias, out);
}